// round 9
// baseline (speedup 1.0000x reference)
#include <cuda_runtime.h>
#include <cuda_bf16.h>

// Problem constants
#define N 4096
#define D 512
#define NC 100          // real classes
#define NCP 128         // padded classes
#define ROWS_B 32       // rows per GEMM block
#define KT 32           // k-tile
#define NBLK (N / ROWS_B)   // 128 gemm blocks (all co-resident: 128 < 148 SMs)

// Packed fp32x2 FMA (Blackwell): d = a*b + d elementwise on 2 floats
#define FMA2(d, a, b) \
    asm("fma.rn.f32x2 %0, %1, %2, %3;" : "=l"(d) : "l"(a), "l"(b), "l"(d))
#define SPLAT2(d, f) \
    asm("mov.b64 %0, {%1, %1};" : "=l"(d) : "f"(f))

// Scratch (device globals; load-time zeroed; gemm tail restores all state to 0
// after every call -> deterministic across graph replays)
__device__ __align__(16) float g_txt_n[N * D];   // normalized text features
__device__ float g_d[N];                          // per-row <img_n, txt_n>
__device__ __align__(16) float g_G[NC * D];       // class sums of img_n, [c][d]
__device__ int    g_cnt[NCP];                     // class counts
__device__ double g_neg;                          // neg accumulator
__device__ double g_sumd;                         // sum_i d_i
__device__ double g_sumexpd;                      // sum_i exp(d_i)
__device__ unsigned int g_fin;                    // epilogue ticket
__device__ unsigned int g_done;                   // "result written" flag
__device__ unsigned int g_cleanfin;               // cleaner ticket

// ---------------------------------------------------------------------------
// Kernel 1: normalize, store txt_n + d_i, scatter img_n into G (v4 REDG).
// grid = N blocks, 128 threads (thread owns 4 consecutive dims, float4).
// ---------------------------------------------------------------------------
__global__ void __launch_bounds__(128) rownorm_kernel(
    const float* __restrict__ img,
    const float* __restrict__ txt,
    const int* __restrict__ labels)
{
    const int i    = blockIdx.x;
    const int tid  = threadIdx.x;
    const int lane = tid & 31;
    const int warp = tid >> 5;

    const float4 a = reinterpret_cast<const float4*>(img + (size_t)i * D)[tid];
    const float4 b = reinterpret_cast<const float4*>(txt + (size_t)i * D)[tid];

    float sii = a.x*a.x + a.y*a.y + a.z*a.z + a.w*a.w;
    float stt = b.x*b.x + b.y*b.y + b.z*b.z + b.w*b.w;
    float sit = a.x*b.x + a.y*b.y + a.z*b.z + a.w*b.w;

    #pragma unroll
    for (int off = 16; off > 0; off >>= 1) {
        sii += __shfl_xor_sync(0xffffffffu, sii, off);
        stt += __shfl_xor_sync(0xffffffffu, stt, off);
        sit += __shfl_xor_sync(0xffffffffu, sit, off);
    }
    __shared__ float red[3][4];
    if (lane == 0) { red[0][warp] = sii; red[1][warp] = stt; red[2][warp] = sit; }
    __syncthreads();
    sii = red[0][0] + red[0][1] + red[0][2] + red[0][3];
    stt = red[1][0] + red[1][1] + red[1][2] + red[1][3];
    sit = red[2][0] + red[2][1] + red[2][2] + red[2][3];

    const float rimg = rsqrtf(sii);
    const float rtxt = rsqrtf(stt);
    int c = labels[i];
    c = min(max(c, 0), NC - 1);

    float4 tn;
    tn.x = b.x * rtxt; tn.y = b.y * rtxt; tn.z = b.z * rtxt; tn.w = b.w * rtxt;
    reinterpret_cast<float4*>(g_txt_n + (size_t)i * D)[tid] = tn;

    // one vector reduction (16B-aligned) instead of 4 scalar REDs
    float* gc = g_G + (size_t)c * D + tid * 4;
    asm volatile("red.global.add.v4.f32 [%0], {%1, %2, %3, %4};"
                 :: "l"(gc), "f"(a.x * rimg), "f"(a.y * rimg),
                    "f"(a.z * rimg), "f"(a.w * rimg)
                 : "memory");

    if (tid == 0) {
        g_d[i] = sit * rimg * rtxt;
        atomicAdd(&g_cnt[c], 1);
    }
}

// ---------------------------------------------------------------------------
// Kernel 2: gemm + neg + folded finish + self-cleaning tail.
// grid = 128 blocks, 256 threads.
// Warp w owns rows 4w..4w+3; lane L owns class pairs (2L,2L+1),(2L+64,2L+65).
// ---------------------------------------------------------------------------
__global__ void __launch_bounds__(256) gemm_neg_kernel(float* __restrict__ out)
{
    __shared__ float As[ROWS_B][KT + 1];   // [row][k], broadcast reads
    __shared__ float Bs[KT][NCP + 2];      // [k][class], stride 130
    __shared__ double bred[8][3];          // per-warp {neg, sumd, sumexp}

    const int tid  = threadIdx.x;
    const int lane = tid & 31;
    const int warp = tid >> 5;
    const int row0 = blockIdx.x * ROWS_B;

    const float n0 = (float)g_cnt[2*lane];
    const float n1 = (float)g_cnt[2*lane + 1];
    const float n2 = (float)g_cnt[2*lane + 64];
    const float n3 = (float)g_cnt[2*lane + 65];

    unsigned long long accp[4][2] = {};

    const int ar  = tid >> 3;            // A row 0..31
    const int ak4 = (tid & 7) * 4;       // A k offset 0..28
    const float4 zero4 = make_float4(0.f, 0.f, 0.f, 0.f);

    float4 aReg;
    float4 bReg[4];

    // prefetch tile 0
    aReg = *reinterpret_cast<const float4*>(&g_txt_n[(size_t)(row0 + ar) * D + ak4]);
    #pragma unroll
    for (int e = 0; e < 4; e++) {
        int idx = tid + e * 256;
        int c = idx >> 3, k4 = (idx & 7) * 4;
        bReg[e] = (c < NC)
            ? *reinterpret_cast<const float4*>(&g_G[(size_t)c * D + k4])
            : zero4;
    }

    for (int t = 0; t < D / KT; t++) {
        As[ar][ak4 + 0] = aReg.x;
        As[ar][ak4 + 1] = aReg.y;
        As[ar][ak4 + 2] = aReg.z;
        As[ar][ak4 + 3] = aReg.w;
        #pragma unroll
        for (int e = 0; e < 4; e++) {
            int idx = tid + e * 256;
            int c = idx >> 3, k4 = (idx & 7) * 4;
            Bs[k4 + 0][c] = bReg[e].x;
            Bs[k4 + 1][c] = bReg[e].y;
            Bs[k4 + 2][c] = bReg[e].z;
            Bs[k4 + 3][c] = bReg[e].w;
        }
        __syncthreads();

        if (t < D / KT - 1) {
            int k0 = (t + 1) * KT;
            aReg = *reinterpret_cast<const float4*>(&g_txt_n[(size_t)(row0 + ar) * D + k0 + ak4]);
            #pragma unroll
            for (int e = 0; e < 4; e++) {
                int idx = tid + e * 256;
                int c = idx >> 3, k4 = (idx & 7) * 4;
                bReg[e] = (c < NC)
                    ? *reinterpret_cast<const float4*>(&g_G[(size_t)c * D + k0 + k4])
                    : zero4;
            }
        }

        #pragma unroll
        for (int kk = 0; kk < KT; kk++) {
            const unsigned long long b0 =
                *reinterpret_cast<const unsigned long long*>(&Bs[kk][2 * lane]);
            const unsigned long long b1 =
                *reinterpret_cast<const unsigned long long*>(&Bs[kk][2 * lane + 64]);
            #pragma unroll
            for (int ii = 0; ii < 4; ii++) {
                float av = As[warp * 4 + ii][kk];
                unsigned long long ap;
                SPLAT2(ap, av);
                FMA2(accp[ii][0], ap, b0);
                FMA2(accp[ii][1], ap, b1);
            }
        }
        __syncthreads();
    }

    // Epilogue: per row i: S = sum_c C[i,c]; neg_i = sum_c n_c * exp(S - C[i,c])
    double warp_neg = 0.0;
    #pragma unroll
    for (int ii = 0; ii < 4; ii++) {
        float c00, c01, c10, c11;
        asm("mov.b64 {%0, %1}, %2;" : "=f"(c00), "=f"(c01) : "l"(accp[ii][0]));
        asm("mov.b64 {%0, %1}, %2;" : "=f"(c10), "=f"(c11) : "l"(accp[ii][1]));
        float s = c00 + c01 + c10 + c11;
        #pragma unroll
        for (int off = 16; off > 0; off >>= 1)
            s += __shfl_xor_sync(0xffffffffu, s, off);   // S_i allreduce
        float p = n0 * expf(s - c00) + n1 * expf(s - c01)
                + n2 * expf(s - c10) + n3 * expf(s - c11);
        #pragma unroll
        for (int off = 16; off > 0; off >>= 1)
            p += __shfl_xor_sync(0xffffffffu, p, off);
        warp_neg += (double)p;
    }

    // warp 0: this block's sumd / sumexpd contribution
    double warp_sd = 0.0, warp_se = 0.0;
    if (warp == 0) {
        const float dv = g_d[row0 + lane];
        double sd = (double)dv;
        double se = (double)expf(dv);
        #pragma unroll
        for (int off = 16; off > 0; off >>= 1) {
            sd += __shfl_xor_sync(0xffffffffu, sd, off);
            se += __shfl_xor_sync(0xffffffffu, se, off);
        }
        warp_sd = sd; warp_se = se;
    }

    if (lane == 0) { bred[warp][0] = warp_neg; bred[warp][1] = warp_sd; bred[warp][2] = warp_se; }
    __syncthreads();

    if (tid == 0) {
        double bneg = 0.0;
        #pragma unroll
        for (int w = 0; w < 8; w++) bneg += bred[w][0];
        atomicAdd(&g_neg, bneg);
        atomicAdd(&g_sumd, bred[0][1]);
        atomicAdd(&g_sumexpd, bred[0][2]);
        __threadfence();
        unsigned t = atomicAdd(&g_fin, 1u);
        if (t == NBLK - 1) {
            // loss = N*log(neg) + sumexp/neg - sumd   (validated, rel_err 9.3e-8)
            const double neg  = atomicAdd(&g_neg, 0.0);
            const double sd   = atomicAdd(&g_sumd, 0.0);
            const double sexp = atomicAdd(&g_sumexpd, 0.0);
            out[0] = (float)((double)N * log(neg) + sexp / neg - sd);
            __threadfence();
            g_done = 1u;               // release: result written, G fully consumed
            __threadfence();
        }
    }

    // ---- self-cleaning tail: restore all device state to 0 for next replay ----
    // All 128 blocks are co-resident (1 block/SM, single wave): read-only spin
    // on g_done is deadlock-free and RMW-free.
    if (tid == 0) {
        while (*(volatile unsigned int*)&g_done == 0u) __nanosleep(64);
    }
    __syncthreads();

    if (tid < 100) {   // block b zeroes its 400-float slice of G (100 float4s)
        const float4 z4 = make_float4(0.f, 0.f, 0.f, 0.f);
        reinterpret_cast<float4*>(g_G)[blockIdx.x * 100 + tid] = z4;
    }
    if (blockIdx.x == 0 && tid < NCP) g_cnt[tid] = 0;
    __threadfence();
    __syncthreads();
    if (tid == 0) {
        unsigned c = atomicAdd(&g_cleanfin, 1u);
        if (c == NBLK - 1) {           // last cleaner resets scalars + flags
            g_neg = 0.0; g_sumd = 0.0; g_sumexpd = 0.0;
            g_fin = 0u; g_cleanfin = 0u;
            __threadfence();
            g_done = 0u;
            __threadfence();
        }
    }
}

// ---------------------------------------------------------------------------
extern "C" void kernel_launch(void* const* d_in, const int* in_sizes, int n_in,
                              void* d_out, int out_size) {
    const float* img    = (const float*)d_in[0];
    const float* txt    = (const float*)d_in[1];
    const int*   labels = (const int*)d_in[2];
    float* out = (float*)d_out;

    rownorm_kernel<<<N, 128>>>(img, txt, labels);
    gemm_neg_kernel<<<NBLK, 256>>>(out);
}

// round 10
// speedup vs baseline: 1.3957x; 1.3957x over previous
#include <cuda_runtime.h>
#include <cuda_bf16.h>

// Problem constants
#define N 4096
#define D 512
#define NC 100          // real classes
#define NCP 128         // padded classes
#define ROWS_B 32       // rows per GEMM block
#define KT 32           // k-tile
#define NBLK (N / ROWS_B)   // 128 gemm blocks

// Scratch (device globals; no allocation in kernel_launch)
__device__ __align__(16) float g_txt_n[N * D];   // normalized text features
__device__ float g_d[N];                          // per-row <img_n, txt_n>
__device__ __align__(16) float g_G[NC * D];       // class sums of img_n, [c][d]
__device__ int    g_cnt[NCP];                     // class counts
__device__ double g_neg;                          // neg accumulator
__device__ double g_sumd;                         // sum_i d_i
__device__ double g_sumexpd;                      // sum_i exp(d_i)
__device__ unsigned int g_fin;                    // epilogue ticket

__device__ __forceinline__ unsigned tf32(float x) {
    unsigned r;
    asm("cvt.rna.tf32.f32 %0, %1;" : "=r"(r) : "f"(x));
    return r;
}

// ---------------------------------------------------------------------------
// Kernel 0: zero scratch accumulators (runs every replay)
// ---------------------------------------------------------------------------
__global__ void zero_kernel() {
    const int idx = blockIdx.x * blockDim.x + threadIdx.x;
    const float4 z4 = make_float4(0.f, 0.f, 0.f, 0.f);
    if (idx < (NC * D) / 4) reinterpret_cast<float4*>(g_G)[idx] = z4;
    if (idx < NCP)          g_cnt[idx] = 0;
    if (idx == 0) { g_neg = 0.0; g_sumd = 0.0; g_sumexpd = 0.0; g_fin = 0u; }
}

// ---------------------------------------------------------------------------
// Kernel 1 (R8-proven): normalize, store txt_n + d_i, scatter img_n into G.
// grid = N blocks, 128 threads (thread owns 4 consecutive dims, float4).
// ---------------------------------------------------------------------------
__global__ void __launch_bounds__(128) rownorm_kernel(
    const float* __restrict__ img,
    const float* __restrict__ txt,
    const int* __restrict__ labels)
{
    const int i    = blockIdx.x;
    const int tid  = threadIdx.x;
    const int lane = tid & 31;
    const int warp = tid >> 5;

    const float4 a = reinterpret_cast<const float4*>(img + (size_t)i * D)[tid];
    const float4 b = reinterpret_cast<const float4*>(txt + (size_t)i * D)[tid];

    float sii = a.x*a.x + a.y*a.y + a.z*a.z + a.w*a.w;
    float stt = b.x*b.x + b.y*b.y + b.z*b.z + b.w*b.w;
    float sit = a.x*b.x + a.y*b.y + a.z*b.z + a.w*b.w;

    #pragma unroll
    for (int off = 16; off > 0; off >>= 1) {
        sii += __shfl_xor_sync(0xffffffffu, sii, off);
        stt += __shfl_xor_sync(0xffffffffu, stt, off);
        sit += __shfl_xor_sync(0xffffffffu, sit, off);
    }
    __shared__ float red[3][4];
    if (lane == 0) { red[0][warp] = sii; red[1][warp] = stt; red[2][warp] = sit; }
    __syncthreads();
    sii = red[0][0] + red[0][1] + red[0][2] + red[0][3];
    stt = red[1][0] + red[1][1] + red[1][2] + red[1][3];
    sit = red[2][0] + red[2][1] + red[2][2] + red[2][3];

    const float rimg = rsqrtf(sii);
    const float rtxt = rsqrtf(stt);
    int c = labels[i];
    c = min(max(c, 0), NC - 1);

    float4 tn;
    tn.x = b.x * rtxt; tn.y = b.y * rtxt; tn.z = b.z * rtxt; tn.w = b.w * rtxt;
    reinterpret_cast<float4*>(g_txt_n + (size_t)i * D)[tid] = tn;

    // one vector reduction (16B-aligned) instead of 4 scalar REDs
    float* gc = g_G + (size_t)c * D + tid * 4;
    asm volatile("red.global.add.v4.f32 [%0], {%1, %2, %3, %4};"
                 :: "l"(gc), "f"(a.x * rimg), "f"(a.y * rimg),
                    "f"(a.z * rimg), "f"(a.w * rimg)
                 : "memory");

    if (tid == 0) {
        g_d[i] = sit * rimg * rtxt;
        atomicAdd(&g_cnt[c], 1);
    }
}

// ---------------------------------------------------------------------------
// Kernel 2: tf32 tensor-core GEMM (C = txt_n @ G^T) + neg + folded finish.
// grid = 128 blocks, 256 threads (8 warps).
// Warp (m = w&1, nq = w>>1) owns rows 16m..16m+15 x classes 32nq..32nq+31.
// mma.sync.m16n8k8.tf32: per 8-k subtile: 4 A LDS + 8 B LDS + 4 mma,
// all smem reads bank-conflict-free (row stride 36 floats).
// ---------------------------------------------------------------------------
__global__ void __launch_bounds__(256) gemm_neg_kernel(float* __restrict__ out)
{
    __shared__ float As[ROWS_B][36];   // [row][k], tf32 bits, K-major
    __shared__ float Bs[NCP][36];      // [class][k], tf32 bits, K-major
    __shared__ float nsm[NCP];         // class counts as float
    __shared__ float Ssm[ROWS_B][4];   // per-row partial sums per class-quadrant
    __shared__ double bred[8][3];      // per-warp {neg, sumd, sumexp}

    const int tid  = threadIdx.x;
    const int lane = tid & 31;
    const int warp = tid >> 5;
    const int g    = lane >> 2;        // group id 0..7
    const int tig  = lane & 3;         // thread in group 0..3
    const int m    = warp & 1;         // row half
    const int nq   = warp >> 1;        // class quadrant 0..3
    const int row0 = blockIdx.x * ROWS_B;

    if (tid < NCP) nsm[tid] = (float)g_cnt[tid];

    float acc[4][4] = {};              // [n-tile][c0..c3]

    // staging addressing (constant per thread)
    const int ar  = tid >> 3;          // A row 0..31
    const int ak4 = (tid & 7) * 4;     // k offset 0..28
    const float4 zero4 = make_float4(0.f, 0.f, 0.f, 0.f);

    float4 aReg;
    float4 bReg[4];

    // prefetch tile 0
    aReg = *reinterpret_cast<const float4*>(&g_txt_n[(size_t)(row0 + ar) * D + ak4]);
    #pragma unroll
    for (int e = 0; e < 4; e++) {
        int idx = tid + e * 256;
        int c = idx >> 3, k4 = (idx & 7) * 4;
        bReg[e] = (c < NC)
            ? *reinterpret_cast<const float4*>(&g_G[(size_t)c * D + k4])
            : zero4;
    }

    for (int t = 0; t < D / KT; t++) {
        // commit prefetched tile to smem as tf32 bits (float4 STS.128)
        {
            float4 av;
            av.x = __uint_as_float(tf32(aReg.x));
            av.y = __uint_as_float(tf32(aReg.y));
            av.z = __uint_as_float(tf32(aReg.z));
            av.w = __uint_as_float(tf32(aReg.w));
            *reinterpret_cast<float4*>(&As[ar][ak4]) = av;
        }
        #pragma unroll
        for (int e = 0; e < 4; e++) {
            int idx = tid + e * 256;
            int c = idx >> 3, k4 = (idx & 7) * 4;
            float4 bv;
            bv.x = __uint_as_float(tf32(bReg[e].x));
            bv.y = __uint_as_float(tf32(bReg[e].y));
            bv.z = __uint_as_float(tf32(bReg[e].z));
            bv.w = __uint_as_float(tf32(bReg[e].w));
            *reinterpret_cast<float4*>(&Bs[c][k4]) = bv;
        }
        __syncthreads();

        // prefetch next tile (overlaps compute)
        if (t < D / KT - 1) {
            int k0 = (t + 1) * KT;
            aReg = *reinterpret_cast<const float4*>(&g_txt_n[(size_t)(row0 + ar) * D + k0 + ak4]);
            #pragma unroll
            for (int e = 0; e < 4; e++) {
                int idx = tid + e * 256;
                int c = idx >> 3, k4 = (idx & 7) * 4;
                bReg[e] = (c < NC)
                    ? *reinterpret_cast<const float4*>(&g_G[(size_t)c * D + k0 + k4])
                    : zero4;
            }
        }

        // compute: 4 k-subtiles of 8
        #pragma unroll
        for (int ks = 0; ks < 4; ks++) {
            const int kk0 = ks * 8;
            const unsigned a0 = __float_as_uint(As[16*m + g    ][kk0 + tig]);
            const unsigned a1 = __float_as_uint(As[16*m + g + 8][kk0 + tig]);
            const unsigned a2 = __float_as_uint(As[16*m + g    ][kk0 + tig + 4]);
            const unsigned a3 = __float_as_uint(As[16*m + g + 8][kk0 + tig + 4]);
            #pragma unroll
            for (int nt = 0; nt < 4; nt++) {
                const int cb = 32*nq + 8*nt + g;
                const unsigned b0 = __float_as_uint(Bs[cb][kk0 + tig]);
                const unsigned b1 = __float_as_uint(Bs[cb][kk0 + tig + 4]);
                asm volatile(
                    "mma.sync.aligned.m16n8k8.row.col.f32.tf32.tf32.f32 "
                    "{%0,%1,%2,%3}, {%4,%5,%6,%7}, {%8,%9}, {%0,%1,%2,%3};"
                    : "+f"(acc[nt][0]), "+f"(acc[nt][1]),
                      "+f"(acc[nt][2]), "+f"(acc[nt][3])
                    : "r"(a0), "r"(a1), "r"(a2), "r"(a3), "r"(b0), "r"(b1));
            }
        }
        __syncthreads();
    }

    // ---- Epilogue ----
    // Thread holds C at rows r0=16m+g, r1=r0+8; cols 32nq+8nt+2tig(+1).
    // pass 1: per-row partial sums over this warp's 32 classes
    float s0 = 0.f, s1 = 0.f;
    #pragma unroll
    for (int nt = 0; nt < 4; nt++) {
        s0 += acc[nt][0] + acc[nt][1];
        s1 += acc[nt][2] + acc[nt][3];
    }
    // reduce across the 4 threads sharing each row (tig dimension = low 2 lane bits)
    s0 += __shfl_xor_sync(0xffffffffu, s0, 1);
    s0 += __shfl_xor_sync(0xffffffffu, s0, 2);
    s1 += __shfl_xor_sync(0xffffffffu, s1, 1);
    s1 += __shfl_xor_sync(0xffffffffu, s1, 2);
    const int r0 = 16*m + g, r1 = r0 + 8;
    if (tig == 0) { Ssm[r0][nq] = s0; Ssm[r1][nq] = s1; }
    __syncthreads();

    // pass 2: neg contributions with full S
    const float S0 = Ssm[r0][0] + Ssm[r0][1] + Ssm[r0][2] + Ssm[r0][3];
    const float S1 = Ssm[r1][0] + Ssm[r1][1] + Ssm[r1][2] + Ssm[r1][3];
    float p = 0.f;
    #pragma unroll
    for (int nt = 0; nt < 4; nt++) {
        const int cA = 32*nq + 8*nt + 2*tig;
        const float nA = nsm[cA], nB = nsm[cA + 1];
        p += nA * expf(S0 - acc[nt][0]) + nB * expf(S0 - acc[nt][1]);
        p += nA * expf(S1 - acc[nt][2]) + nB * expf(S1 - acc[nt][3]);
    }
    #pragma unroll
    for (int off = 16; off > 0; off >>= 1)
        p += __shfl_xor_sync(0xffffffffu, p, off);
    const double warp_neg = (double)p;

    // warp 0: this block's sumd / sumexpd contribution
    double warp_sd = 0.0, warp_se = 0.0;
    if (warp == 0) {
        const float dv = g_d[row0 + lane];
        double sd = (double)dv;
        double se = (double)expf(dv);
        #pragma unroll
        for (int off = 16; off > 0; off >>= 1) {
            sd += __shfl_xor_sync(0xffffffffu, sd, off);
            se += __shfl_xor_sync(0xffffffffu, se, off);
        }
        warp_sd = sd; warp_se = se;
    }

    if (lane == 0) { bred[warp][0] = warp_neg; bred[warp][1] = warp_sd; bred[warp][2] = warp_se; }
    __syncthreads();

    if (tid == 0) {
        double bneg = 0.0;
        #pragma unroll
        for (int w = 0; w < 8; w++) bneg += bred[w][0];
        atomicAdd(&g_neg, bneg);
        atomicAdd(&g_sumd, bred[0][1]);
        atomicAdd(&g_sumexpd, bred[0][2]);
        __threadfence();
        unsigned t = atomicAdd(&g_fin, 1u);
        if (t == NBLK - 1) {
            // loss = N*log(neg) + sumexp/neg - sumd
            // (sum_i log1p(exp(d_i)/neg) == sumexp/neg to ~1e-10 abs since
            //  neg >= ~1e5 and exp(d_i) <= e; validated across rounds)
            const double neg  = atomicAdd(&g_neg, 0.0);
            const double sd   = atomicAdd(&g_sumd, 0.0);
            const double sexp = atomicAdd(&g_sumexpd, 0.0);
            out[0] = (float)((double)N * log(neg) + sexp / neg - sd);
        }
    }
}

// ---------------------------------------------------------------------------
extern "C" void kernel_launch(void* const* d_in, const int* in_sizes, int n_in,
                              void* d_out, int out_size) {
    const float* img    = (const float*)d_in[0];
    const float* txt    = (const float*)d_in[1];
    const int*   labels = (const int*)d_in[2];
    float* out = (float*)d_out;

    zero_kernel<<<((NC * D) / 4 + 255) / 256, 256>>>();
    rownorm_kernel<<<N, 128>>>(img, txt, labels);
    gemm_neg_kernel<<<NBLK, 256>>>(out);
}